// round 17
// baseline (speedup 1.0000x reference)
#include <cuda_runtime.h>
#include <cuda_fp16.h>
#include <cuda_bf16.h>

// GNN_Attention: N=50000, E=800000, IN=8, ED=2, H=2, C=64, HID=64, OUT=2
#define MAXN 50000
#define MAXE 800000
#define HC   128
#define HID  64
#define NEG_SLOPE 0.2f

// -------- static device scratch --------
__device__ __align__(16) __half g_xl[MAXN * HC];   // logit operand (fp16)
__device__ __align__(16) __half g_xr[MAXN * HC];   // logit operand (fp16)
__device__ __align__(16) __half g_xh[MAXN * 8];    // fp16 copy of x (message moment)
__device__ __align__(16) float  g_expl[MAXE * 2];
__device__ __align__(16) float  g_denom[MAXN * 2];
__device__ __align__(16) float  g_t[MAXN * 16];    // Σ p_h·x[src]: [n][h][i], fp32
__device__ __align__(16) __half g_hw[MAXN * HID];  // (h @ gcn_W.T) * indicator
__device__ __align__(16) float  g_h2acc[MAXN * HID];

__device__ __forceinline__ void red_add_v4(float* p, float4 v) {
    asm volatile("red.global.add.v4.f32 [%0], {%1,%2,%3,%4};"
                 :: "l"(p), "f"(v.x), "f"(v.y), "f"(v.z), "f"(v.w)
                 : "memory");
}
__device__ __forceinline__ void red_add_v2(float* p, float a, float b) {
    asm volatile("red.global.add.v2.f32 [%0], {%1,%2};"
                 :: "l"(p), "f"(a), "f"(b)
                 : "memory");
}
__device__ __forceinline__ float4 ld_half4(const __half* base, int idx8) {
    uint2 raw = ((const uint2*)base)[idx8];
    __half2 h01 = *reinterpret_cast<__half2*>(&raw.x);
    __half2 h23 = *reinterpret_cast<__half2*>(&raw.y);
    float2 f01 = __half22float2(h01);
    float2 f23 = __half22float2(h23);
    return make_float4(f01.x, f01.y, f23.x, f23.y);
}
// unpack 8 halves (one uint4) to 8 floats
__device__ __forceinline__ void unpack8(uint4 raw, float* f) {
    __half2 h0 = *reinterpret_cast<__half2*>(&raw.x);
    __half2 h1 = *reinterpret_cast<__half2*>(&raw.y);
    __half2 h2 = *reinterpret_cast<__half2*>(&raw.z);
    __half2 h3 = *reinterpret_cast<__half2*>(&raw.w);
    float2 a = __half22float2(h0); f[0] = a.x; f[1] = a.y;
    float2 b = __half22float2(h1); f[2] = b.x; f[3] = b.y;
    float2 c = __half22float2(h2); f[4] = c.x; f[5] = c.y;
    float2 d = __half22float2(h3); f[6] = d.x; f[7] = d.y;
}

// -------- 1. node projections + zero accumulators + fp16 x copy --------
__global__ void k_proj(const float* __restrict__ x,
                       const float* __restrict__ Wl, const float* __restrict__ bl,
                       const float* __restrict__ Wr, const float* __restrict__ br,
                       int N) {
    int idx = blockIdx.x * blockDim.x + threadIdx.x;
    if (idx >= N * HC) return;
    if (idx < N * 16)  g_t[idx]     = 0.f;
    if (idx < N * HID) g_h2acc[idx] = 0.f;
    if (idx < N * 2)   g_denom[idx] = 0.f;
    if (idx < N * 8)   g_xh[idx]    = __float2half(x[idx]);

    int n = idx >> 7, ch = idx & 127;
    const float* xv = x + n * 8;
    float sl = bl[ch], sr = br[ch];
    #pragma unroll
    for (int i = 0; i < 8; i++) {
        float xi = xv[i];
        sl += xi * Wl[ch * 8 + i];
        sr += xi * Wr[ch * 8 + i];
    }
    g_xl[idx] = __float2half(sl);
    g_xr[idx] = __float2half(sr);
}

// -------- 2. logits: 16 lanes/edge (8 channels/lane), 2 edges concurrent ----
// Same math as before; re-layout halves LDG count and shrinks the shuffle
// reduction to width 8. Moment scatter: t[dst][h] += p_h * x[src].
__global__ void k_logits(const int* __restrict__ ei,
                         const float* __restrict__ ea,
                         const float* __restrict__ We,
                         const float* __restrict__ att, int E) {
    int warp = (blockIdx.x * blockDim.x + threadIdx.x) >> 5;
    int lane = threadIdx.x & 31;
    int e0 = warp * 4;
    if (e0 >= E) return;
    int half = lane >> 4;      // which of 2 concurrent edges
    int li   = lane & 15;      // channel group: ch = li*8 .. li*8+7

    // per-lane constants: 8 channels
    float4 at0 = ((const float4*)att)[li * 2];
    float4 at1 = ((const float4*)att)[li * 2 + 1];
    float4 w0  = ((const float4*)We)[li * 4];
    float4 w1  = ((const float4*)We)[li * 4 + 1];
    float4 w2  = ((const float4*)We)[li * 4 + 2];
    float4 w3  = ((const float4*)We)[li * 4 + 3];

    int src[2], dst[2];
    float2 eav[2];
    #pragma unroll
    for (int j = 0; j < 2; j++) {
        int e = min(e0 + 2 * j + half, E - 1);
        src[j] = ei[e];
        dst[j] = ei[E + e];
        eav[j] = ((const float2*)ea)[e];
    }
    uint4 xlr[2], xrr[2];
    #pragma unroll
    for (int j = 0; j < 2; j++) xlr[j] = ((const uint4*)g_xl)[src[j] * 16 + li];
    #pragma unroll
    for (int j = 0; j < 2; j++) xrr[j] = ((const uint4*)g_xr)[dst[j] * 16 + li];

    float s[2];
    #pragma unroll
    for (int j = 0; j < 2; j++) {
        float a[8], b[8];
        unpack8(xlr[j], a);
        unpack8(xrr[j], b);
        float ex0 = eav[j].x, ex1 = eav[j].y;
        float ep[8];
        ep[0] = w0.x * ex0 + w0.y * ex1;  ep[1] = w0.z * ex0 + w0.w * ex1;
        ep[2] = w1.x * ex0 + w1.y * ex1;  ep[3] = w1.z * ex0 + w1.w * ex1;
        ep[4] = w2.x * ex0 + w2.y * ex1;  ep[5] = w2.z * ex0 + w2.w * ex1;
        ep[6] = w3.x * ex0 + w3.y * ex1;  ep[7] = w3.z * ex0 + w3.w * ex1;
        float atv[8] = {at0.x, at0.y, at0.z, at0.w, at1.x, at1.y, at1.z, at1.w};
        float acc = 0.f;
        #pragma unroll
        for (int c = 0; c < 8; c++) {
            float z = a[c] + b[c] + ep[c];
            z = z > 0.f ? z : NEG_SLOPE * z;
            acc += z * atv[c];
        }
        s[j] = acc;
    }
    // reduce within 8-lane head groups (lanes 0-7: head0, 8-15: head1, per half)
    #pragma unroll
    for (int o = 4; o >= 1; o >>= 1) {
        s[0] += __shfl_xor_sync(0xffffffffu, s[0], o, 8);
        s[1] += __shfl_xor_sync(0xffffffffu, s[1], o, 8);
    }
    float p[2], pd[2];
    #pragma unroll
    for (int j = 0; j < 2; j++) p[j] = __expf(s[j]);  // |logit| small: no max-sub
    #pragma unroll
    for (int j = 0; j < 2; j++) pd[j] = __shfl_down_sync(0xffffffffu, p[j], 8, 16);
    // now lanes li<8 hold (p = head0, pd = head1) for their half's edge

    #pragma unroll
    for (int j = 0; j < 2; j++) {
        int e = e0 + 2 * j + half;
        if (li == 0 && e < E) {
            ((float2*)g_expl)[e] = make_float2(p[j], pd[j]);
            red_add_v2(&g_denom[2 * dst[j]], p[j], pd[j]);
        }
    }
    // moment scatter: lanes li 0-3 per half; q: {head=q>>1, xpart=q&1}
    #pragma unroll
    for (int j = 0; j < 2; j++) {
        int e = e0 + 2 * j + half;
        if (li < 4 && e < E) {
            int q = li;
            float ps = (q < 2) ? p[j] : pd[j];
            uint4 raw = ((const uint4*)g_xh)[src[j]];
            unsigned u0 = (q & 1) ? raw.z : raw.x;
            unsigned u1 = (q & 1) ? raw.w : raw.y;
            __half2 h01 = *reinterpret_cast<__half2*>(&u0);
            __half2 h23 = *reinterpret_cast<__half2*>(&u1);
            float2 f01 = __half22float2(h01);
            float2 f23 = __half22float2(h23);
            float4 v = make_float4(ps * f01.x, ps * f01.y, ps * f23.x, ps * f23.y);
            red_add_v4(&g_t[dst[j] * 16 + (q >> 1) * 8 + (q & 1) * 4], v);
        }
    }
}

// -------- 3. node GEMM: reconstruct h from t, then h @ gcn_W.T --------
#define NHB 64
#define WP  68
__global__ void k_node_hw(const float* __restrict__ gat_bias,
                          const float* __restrict__ gcn_W,
                          const float* __restrict__ Wl,
                          const float* __restrict__ bl, int N) {
    __shared__ __align__(16) float Wsh[64 * WP];
    __shared__ __align__(16) float hsh[64 * WP];
    __shared__ float Wlsh[HC * 9];
    __shared__ __align__(16) float tsh[NHB * 16];
    __shared__ float inv0[NHB], inv1[NHB], dsh[NHB];
    __shared__ float bsh[HC], blsh[HC];
    int t = threadIdx.x;                 // 256
    int base = blockIdx.x * NHB;

    if (t < HC) { bsh[t] = gat_bias[t]; blsh[t] = bl[t]; }
    for (int i = t; i < HC * 8; i += 256) {
        int row = i >> 3, col = i & 7;
        Wlsh[row * 9 + col] = Wl[i];
    }
    for (int i = t; i < NHB * 16; i += 256) {
        int gi = base * 16 + i;
        tsh[i] = (gi < N * 16) ? g_t[gi] : 0.f;
    }
    if (t < NHB) {
        int n = base + t;
        if (n < N) {
            float2 dn = ((const float2*)g_denom)[n];
            inv0[t] = dn.x > 0.f ? __fdividef(1.f, dn.x) : 0.f;
            inv1[t] = dn.y > 0.f ? __fdividef(1.f, dn.y) : 0.f;
            dsh[t]  = dn.x > 0.f ? 1.f : 0.f;
        } else { inv0[t] = 0.f; inv1[t] = 0.f; dsh[t] = 0.f; }
    }
    __syncthreads();

    int tx = t & 15;
    int ty = t >> 4;
    float acc[4][4];
    #pragma unroll
    for (int i = 0; i < 4; i++)
        #pragma unroll
        for (int j = 0; j < 4; j++) acc[i][j] = 0.f;

    #pragma unroll
    for (int ph = 0; ph < 2; ph++) {
        {
            int k = t & 63, cb = t >> 6;
            #pragma unroll
            for (int j = 0; j < 16; j++) {
                int c = cb + j * 4;
                Wsh[k * WP + c] = gcn_W[c * HC + ph * 64 + k];
            }
        }
        {
            int c = t & 63, nb = t >> 6;
            int ch = ph * 64 + c;
            #pragma unroll
            for (int j = 0; j < 16; j++) {
                int nl = nb + j * 4;
                float iv = ph ? inv1[nl] : inv0[nl];
                const float* tp = &tsh[nl * 16 + ph * 8];
                const float* wp = &Wlsh[ch * 9];
                float td = tp[0] * wp[0] + tp[1] * wp[1] + tp[2] * wp[2] + tp[3] * wp[3]
                         + tp[4] * wp[4] + tp[5] * wp[5] + tp[6] * wp[6] + tp[7] * wp[7];
                hsh[c * WP + nl] =
                    fmaxf(td * iv + dsh[nl] * blsh[ch] + bsh[ch], 0.f);
            }
        }
        __syncthreads();
        #pragma unroll 4
        for (int k = 0; k < 64; k++) {
            float4 w = *(const float4*)&Wsh[k * WP + tx * 4];
            float4 h = *(const float4*)&hsh[k * WP + ty * 4];
            acc[0][0] += h.x * w.x; acc[0][1] += h.x * w.y;
            acc[0][2] += h.x * w.z; acc[0][3] += h.x * w.w;
            acc[1][0] += h.y * w.x; acc[1][1] += h.y * w.y;
            acc[1][2] += h.y * w.z; acc[1][3] += h.y * w.w;
            acc[2][0] += h.z * w.x; acc[2][1] += h.z * w.y;
            acc[2][2] += h.z * w.z; acc[2][3] += h.z * w.w;
            acc[3][0] += h.w * w.x; acc[3][1] += h.w * w.y;
            acc[3][2] += h.w * w.z; acc[3][3] += h.w * w.w;
        }
        __syncthreads();
    }
    #pragma unroll
    for (int i = 0; i < 4; i++) {
        int nl = ty * 4 + i;
        int n = base + nl;
        if (n < N) {
            float di = dsh[nl];
            __half2 o01 = __floats2half2_rn(acc[i][0] * di, acc[i][1] * di);
            __half2 o23 = __floats2half2_rn(acc[i][2] * di, acc[i][3] * di);
            uint2 raw;
            raw.x = *reinterpret_cast<unsigned int*>(&o01);
            raw.y = *reinterpret_cast<unsigned int*>(&o23);
            ((uint2*)g_hw)[n * 16 + tx] = raw;
        }
    }
}

// -------- 4. fused alpha + GCN edge scatter --------
__global__ void k_gcn_edge(const int* __restrict__ ei,
                           float* __restrict__ alpha_out, int E) {
    int warp = (blockIdx.x * blockDim.x + threadIdx.x) >> 5;
    int lane = threadIdx.x & 31;
    int half = lane >> 4;
    int l    = lane & 15;
    int e0 = warp * 8 + half;
    if (e0 >= E) return;

    int src[4], dst[4];
    #pragma unroll
    for (int j = 0; j < 4; j++) {
        int e = min(e0 + 2 * j, E - 1);
        src[j] = ei[e];
        dst[j] = ei[E + e];
    }
    float2 pe[4];
    #pragma unroll
    for (int j = 0; j < 4; j++) pe[j] = ((const float2*)g_expl)[min(e0 + 2 * j, E - 1)];
    float2 dn[4];
    #pragma unroll
    for (int j = 0; j < 4; j++) dn[j] = ((const float2*)g_denom)[dst[j]];

    float nv[4];
    #pragma unroll
    for (int j = 0; j < 4; j++) {
        float a0 = __fdividef(pe[j].x, dn[j].x);
        float a1 = __fdividef(pe[j].y, dn[j].y);
        nv[j] = 0.5f * (a0 + a1);
        int e = e0 + 2 * j;
        if (l == 0 && e < E)
            ((float2*)alpha_out)[e] = make_float2(a0, a1);
    }
    float4 v[4];
    #pragma unroll
    for (int j = 0; j < 4; j++)
        v[j] = ld_half4(g_hw, src[j] * 16 + l);
    #pragma unroll
    for (int j = 0; j < 4; j++) {
        if (e0 + 2 * j < E) {
            float4 m = v[j];
            m.x *= nv[j]; m.y *= nv[j]; m.z *= nv[j]; m.w *= nv[j];
            red_add_v4(&g_h2acc[dst[j] * HID + l * 4], m);
        }
    }
}

// -------- 5. per-node output --------
__global__ void k_node_out(const float* __restrict__ gcn_b,
                           const float* __restrict__ out_W,
                           const float* __restrict__ out_b,
                           float* __restrict__ out, int N) {
    int t = blockIdx.x * blockDim.x + threadIdx.x;
    int n = t >> 5;
    if (n >= N) return;
    int lane = t & 31;
    float2 hv = ((const float2*)g_h2acc)[n * 32 + lane];
    float h0 = fmaxf(hv.x + gcn_b[2 * lane],     0.f);
    float h1 = fmaxf(hv.y + gcn_b[2 * lane + 1], 0.f);
    float s0 = h0 * out_W[2 * lane]      + h1 * out_W[2 * lane + 1];
    float s1 = h0 * out_W[64 + 2 * lane] + h1 * out_W[64 + 2 * lane + 1];
    #pragma unroll
    for (int o = 16; o >= 1; o >>= 1) {
        s0 += __shfl_down_sync(0xffffffffu, s0, o);
        s1 += __shfl_down_sync(0xffffffffu, s1, o);
    }
    if (lane == 0) {
        out[2 * n]     = s0 + out_b[0];
        out[2 * n + 1] = s1 + out_b[1];
    }
}

extern "C" void kernel_launch(void* const* d_in, const int* in_sizes, int n_in,
                              void* d_out, int out_size) {
    const float* x        = (const float*)d_in[0];
    const float* ea       = (const float*)d_in[1];
    const int*   ei       = (const int*)d_in[2];   // int32 (JAX x64 disabled)
    const float* Wl       = (const float*)d_in[3];
    const float* bl       = (const float*)d_in[4];
    const float* Wr       = (const float*)d_in[5];
    const float* br       = (const float*)d_in[6];
    const float* We       = (const float*)d_in[7];
    const float* att      = (const float*)d_in[8];
    const float* gat_bias = (const float*)d_in[9];
    const float* gcn_W    = (const float*)d_in[10];
    const float* gcn_b    = (const float*)d_in[11];
    const float* out_W    = (const float*)d_in[12];
    const float* out_b    = (const float*)d_in[13];

    int N = in_sizes[0] / 8;     // IN=8
    int E = in_sizes[1] / 2;     // ED=2

    float* out       = (float*)d_out;
    float* alpha_out = (float*)d_out + (size_t)N * 2;

    const int NT = 256;
    int warpsL = (E + 3) / 4;   // 4 edges/warp
    int warpsG = (E + 7) / 8;   // 8 edges/warp
    k_proj<<<(N * HC + NT - 1) / NT, NT>>>(x, Wl, bl, Wr, br, N);
    k_logits<<<(int)(((size_t)warpsL * 32 + NT - 1) / NT), NT>>>(ei, ea, We, att, E);
    k_node_hw<<<(N + NHB - 1) / NHB, 256>>>(gat_bias, gcn_W, Wl, bl, N);
    k_gcn_edge<<<(int)(((size_t)warpsG * 32 + NT - 1) / NT), NT>>>(ei, alpha_out, E);
    k_node_out<<<(int)(((size_t)N * 32 + NT - 1) / NT), NT>>>(gcn_b, out_W, out_b, out, N);
}